// round 16
// baseline (speedup 1.0000x reference)
#include <cuda_runtime.h>
#include <cuda_bf16.h>
#include <cstdint>

#define HN 16
#define BN_ 2
#define SN 2048
#define DN 1024
#define EN 64
#define BSN 4096
#define HBN 32

// ---------------- device scratch (allocation-free rule) ----------------
__device__ __align__(256) __nv_bfloat16 g_w_hi[4][DN * DN];   // [z][n][k]
__device__ __align__(256) __nv_bfloat16 g_w_lo[4][DN * DN];
__device__ __align__(256) __nv_bfloat16 g_x_hi[3][BSN * DN];  // q/k/v split [b*S+s][d]
__device__ __align__(256) __nv_bfloat16 g_x_lo[3][BSN * DN];
__device__ __align__(256) __nv_bfloat16 g_p_hi[3][BSN * DN];  // qh/kh/vh split
__device__ __align__(256) __nv_bfloat16 g_p_lo[3][BSN * DN];
__device__ __align__(256) __nv_bfloat16 g_vt_hi[HBN][EN * SN]; // V^T per head
__device__ __align__(256) __nv_bfloat16 g_vt_lo[HBN][EN * SN];
__device__ __align__(256) __nv_bfloat16 g_cat_hi[BSN * DN];
__device__ __align__(256) __nv_bfloat16 g_cat_lo[BSN * DN];
__device__ __align__(256) float g_attn_fb[(size_t)HBN * SN * SN];
__device__ __align__(256) float g_part[(size_t)HBN * SN][64]; // per-row 32-col-group exp sums
__device__ __align__(256) float g_inv[HBN * SN];              // 1 / row sum

// ---------------- helpers ----------------
__device__ __forceinline__ uint32_t smem_u32(const void* p) {
    uint32_t a;
    asm("{ .reg .u64 t; cvta.to.shared.u64 t, %1; cvt.u32.u64 %0, t; }" : "=r"(a) : "l"(p));
    return a;
}
#define SWZ(x) ((x) ^ (((x) >> 3) & 0x70))

__device__ __forceinline__ void sts128(uint32_t addr, uint4 v) {
    asm volatile("st.shared.v4.b32 [%0], {%1,%2,%3,%4};"
                 :: "r"(addr), "r"(v.x), "r"(v.y), "r"(v.z), "r"(v.w) : "memory");
}
__device__ __forceinline__ uint32_t bpair(float a, float b) {
    uint32_t r;
    asm("cvt.rn.bf16x2.f32 %0, %1, %2;" : "=r"(r) : "f"(b), "f"(a));
    return r;
}
__device__ __forceinline__ void ldmx4(uint32_t* r, uint32_t addr) {
    asm volatile("ldmatrix.sync.aligned.m8n8.x4.shared.b16 {%0,%1,%2,%3}, [%4];"
                 : "=r"(r[0]), "=r"(r[1]), "=r"(r[2]), "=r"(r[3]) : "r"(addr));
}
__device__ __forceinline__ void mma16816(float* d, const uint32_t* a, const uint32_t* b) {
    asm volatile("mma.sync.aligned.m16n8k16.row.col.f32.bf16.bf16.f32 "
        "{%0,%1,%2,%3}, {%4,%5,%6,%7}, {%8,%9}, {%0,%1,%2,%3};"
        : "+f"(d[0]), "+f"(d[1]), "+f"(d[2]), "+f"(d[3])
        : "r"(a[0]), "r"(a[1]), "r"(a[2]), "r"(a[3]), "r"(b[0]), "r"(b[1]));
}
__device__ __forceinline__ void store_split2(__nv_bfloat16* Chi, __nv_bfloat16* Clo,
                                             size_t off, float v0, float v1) {
    float h0 = __bfloat162float(__float2bfloat16(v0));
    float h1 = __bfloat162float(__float2bfloat16(v1));
    *(uint32_t*)(Chi + off) = bpair(h0, h1);
    *(uint32_t*)(Clo + off) = bpair(v0 - h0, v1 - h1);
}

// cp.async 16B
__device__ __forceinline__ void cpa16(uint32_t dst, const void* src) {
    asm volatile("cp.async.cg.shared.global [%0], [%1], 16;" :: "r"(dst), "l"(src) : "memory");
}
#define CP_COMMIT() asm volatile("cp.async.commit_group;" ::: "memory")
#define CP_WAIT1()  asm volatile("cp.async.wait_group 1;" ::: "memory")
#define CP_WAIT0()  asm volatile("cp.async.wait_group 0;" ::: "memory")

__device__ __forceinline__ void cp_tile(uint32_t dst, const __nv_bfloat16* __restrict__ src,
                                        int ld, int tid, int rows) {
    int nchunk = rows * 8;
    for (int c = tid; c < nchunk; c += 256) {
        int r = c >> 3, g = c & 7;
        cpa16(dst + SWZ((uint32_t)(r * 128 + g * 16)), src + (size_t)r * ld + g * 8);
    }
}
__device__ __forceinline__ void load_b16(uint32_t dst, const __nv_bfloat16* __restrict__ src,
                                         int ld, int tid, int rows) {
    int nchunk = rows * 8;
    for (int c = tid; c < nchunk; c += 256) {
        int r = c >> 3, g = c & 7;
        uint4 v = *(const uint4*)(src + (size_t)r * ld + g * 8);
        sts128(dst + SWZ((uint32_t)(r * 128 + g * 16)), v);
    }
}

// global fp32 exp'd attn -> normalize by sinv[row], write back normalized,
// and store normalized split bf16 hi/lo into swizzled smem (128 rows x 64 cols)
__device__ __forceinline__ void storeA_norm(uint32_t dhi, uint32_t dlo,
                                            float* src, int ld, int tid,
                                            const float* sinv) {
#pragma unroll
    for (int it = 0; it < 4; it++) {
        int c = tid + it * 256;
        int r = c >> 3, g = c & 7;
        float* p = src + (size_t)r * ld + g * 8;
        float4 f0 = *(const float4*)p;
        float4 f1 = *(const float4*)(p + 4);
        float inv = sinv[r];
        float v[8] = {f0.x * inv, f0.y * inv, f0.z * inv, f0.w * inv,
                      f1.x * inv, f1.y * inv, f1.z * inv, f1.w * inv};
        // write back normalized attn (each element touched exactly once)
        *(float4*)p       = make_float4(v[0], v[1], v[2], v[3]);
        *(float4*)(p + 4) = make_float4(v[4], v[5], v[6], v[7]);
        uint4 H, L;
        uint32_t* Hp = (uint32_t*)&H;
        uint32_t* Lp = (uint32_t*)&L;
#pragma unroll
        for (int pp = 0; pp < 4; pp++) {
            float h0 = __bfloat162float(__float2bfloat16(v[pp * 2]));
            float h1 = __bfloat162float(__float2bfloat16(v[pp * 2 + 1]));
            Hp[pp] = bpair(h0, h1);
            Lp[pp] = bpair(v[pp * 2] - h0, v[pp * 2 + 1] - h1);
        }
        uint32_t ad = SWZ((uint32_t)(r * 128 + g * 16));
        sts128(dhi + ad, H);
        sts128(dlo + ad, L);
    }
}

// smem layouts
#define NSTAGE 49152
#define SMEM_N64X2 (2 * NSTAGE)   // 96 KB -> 2 CTAs/SM
#define SMEM_SCORES 65536         // 128x128 single stage; 2 CTAs/SM via reg cap

// ===========================================================================
// mma core, 128x64 tile, 8 warps (4x2), warp 32x32. acc[2][4][4].
// ===========================================================================
__device__ __forceinline__ void mma_chunk_64(float acc[2][4][4], uint32_t bs,
                                             int wm, int wn, int lane) {
#pragma unroll
    for (int ks = 0; ks < 4; ks++) {
        uint32_t ah[2][4], al[2][4], bh[4][2], bl[4][2];
        int acol = ks * 32 + (lane >> 4) * 16;
#pragma unroll
        for (int mi = 0; mi < 2; mi++) {
            int arow = wm * 32 + mi * 16 + (lane & 15);
            uint32_t off = SWZ((uint32_t)(arow * 128 + acol));
            ldmx4(ah[mi], bs + off);
            ldmx4(al[mi], bs + 16384 + off);
        }
        int bcol = ks * 32 + ((lane >> 3) & 1) * 16;
#pragma unroll
        for (int nj = 0; nj < 2; nj++) {
            int brow = wn * 32 + nj * 16 + (lane & 7) + (lane >> 4) * 8;
            uint32_t off = SWZ((uint32_t)(brow * 128 + bcol));
            uint32_t t[4];
            ldmx4(t, bs + 32768 + off);
            bh[nj * 2][0] = t[0]; bh[nj * 2][1] = t[1];
            bh[nj * 2 + 1][0] = t[2]; bh[nj * 2 + 1][1] = t[3];
            ldmx4(t, bs + 40960 + off);
            bl[nj * 2][0] = t[0]; bl[nj * 2][1] = t[1];
            bl[nj * 2 + 1][0] = t[2]; bl[nj * 2 + 1][1] = t[3];
        }
#pragma unroll
        for (int mi = 0; mi < 2; mi++)
#pragma unroll
            for (int ni = 0; ni < 4; ni++) {
                mma16816(acc[mi][ni], ah[mi], bh[ni]);
                mma16816(acc[mi][ni], ah[mi], bl[ni]);
                mma16816(acc[mi][ni], al[mi], bh[ni]);
            }
    }
}

// mma core, 128x128 tile (scores), 8 warps (2x4), warp 64x32. acc[4][4][4].
__device__ __forceinline__ void mma_chunk_128(float acc[4][4][4], uint32_t bs,
                                              int wm, int wn, int lane) {
#pragma unroll
    for (int ks = 0; ks < 4; ks++) {
        uint32_t ah[4][4], al[4][4], bh[4][2], bl[4][2];
        int acol = ks * 32 + (lane >> 4) * 16;
#pragma unroll
        for (int mi = 0; mi < 4; mi++) {
            int arow = wm * 64 + mi * 16 + (lane & 15);
            uint32_t off = SWZ((uint32_t)(arow * 128 + acol));
            ldmx4(ah[mi], bs + off);
            ldmx4(al[mi], bs + 16384 + off);
        }
        int bcol = ks * 32 + ((lane >> 3) & 1) * 16;
#pragma unroll
        for (int nj = 0; nj < 2; nj++) {
            int brow = wn * 32 + nj * 16 + (lane & 7) + (lane >> 4) * 8;
            uint32_t off = SWZ((uint32_t)(brow * 128 + bcol));
            uint32_t t[4];
            ldmx4(t, bs + 32768 + off);
            bh[nj * 2][0] = t[0]; bh[nj * 2][1] = t[1];
            bh[nj * 2 + 1][0] = t[2]; bh[nj * 2 + 1][1] = t[3];
            ldmx4(t, bs + 49152 + off);
            bl[nj * 2][0] = t[0]; bl[nj * 2][1] = t[1];
            bl[nj * 2 + 1][0] = t[2]; bl[nj * 2 + 1][1] = t[3];
        }
#pragma unroll
        for (int mi = 0; mi < 4; mi++)
#pragma unroll
            for (int ni = 0; ni < 4; ni++) {
                mma16816(acc[mi][ni], ah[mi], bh[ni]);
                mma16816(acc[mi][ni], ah[mi], bl[ni]);
                mma16816(acc[mi][ni], al[mi], bh[ni]);
            }
    }
}

// ---------------------------------------------------------------------------
// xsplit: q/k/v fp32 -> bf16 hi/lo. grid (2048, 3)
// ---------------------------------------------------------------------------
__global__ void __launch_bounds__(256) xsplit_kernel(
    const float* __restrict__ q, const float* __restrict__ k, const float* __restrict__ v)
{
    int z = blockIdx.y;
    const float* X = (z == 0) ? q : ((z == 1) ? k : v);
    size_t idx = ((size_t)blockIdx.x * 256 + threadIdx.x) * 8;
    float4 f0 = *(const float4*)(X + idx);
    float4 f1 = *(const float4*)(X + idx + 4);
    float val[8] = {f0.x, f0.y, f0.z, f0.w, f1.x, f1.y, f1.z, f1.w};
    uint4 H, L;
    uint32_t* Hp = (uint32_t*)&H;
    uint32_t* Lp = (uint32_t*)&L;
#pragma unroll
    for (int pp = 0; pp < 4; pp++) {
        float h0 = __bfloat162float(__float2bfloat16(val[pp * 2]));
        float h1 = __bfloat162float(__float2bfloat16(val[pp * 2 + 1]));
        Hp[pp] = bpair(h0, h1);
        Lp[pp] = bpair(val[pp * 2] - h0, val[pp * 2 + 1] - h1);
    }
    *(uint4*)(g_x_hi[z] + idx) = H;
    *(uint4*)(g_x_lo[z] + idx) = L;
}

// ---------------------------------------------------------------------------
// Weight transpose+split (unchanged)
// ---------------------------------------------------------------------------
__global__ void __launch_bounds__(256) wsplit_qkv(
    const float* __restrict__ wq, const float* __restrict__ wk, const float* __restrict__ wv)
{
    __shared__ float tile[32][33];
    int z = blockIdx.z >> 4, h = blockIdx.z & 15;
    const float* W = (z == 0) ? wq : ((z == 1) ? wk : wv);
    int d0 = blockIdx.x * 32, e0 = blockIdx.y * 32;
    int tx = threadIdx.x, ty = threadIdx.y;
#pragma unroll
    for (int i = 0; i < 4; i++) {
        int d = d0 + ty + i * 8;
        tile[ty + i * 8][tx] = W[(size_t)h * DN * EN + (size_t)d * EN + e0 + tx];
    }
    __syncthreads();
#pragma unroll
    for (int i = 0; i < 4; i++) {
        int e = e0 + ty + i * 8;
        int n = h * EN + e, k = d0 + tx;
        float v = tile[tx][ty + i * 8];
        float hf = __bfloat162float(__float2bfloat16(v));
        g_w_hi[z][(size_t)n * DN + k] = __float2bfloat16(hf);
        g_w_lo[z][(size_t)n * DN + k] = __float2bfloat16(v - hf);
    }
}

__global__ void __launch_bounds__(256) wsplit_o(const float* __restrict__ wo)
{
    __shared__ float tile[32][33];
    int k0 = blockIdx.x * 32, n0 = blockIdx.y * 32;
    int tx = threadIdx.x, ty = threadIdx.y;
#pragma unroll
    for (int i = 0; i < 4; i++)
        tile[ty + i * 8][tx] = wo[(size_t)(k0 + ty + i * 8) * DN + n0 + tx];
    __syncthreads();
#pragma unroll
    for (int i = 0; i < 4; i++) {
        int n = n0 + ty + i * 8, k = k0 + tx;
        float v = tile[tx][ty + i * 8];
        float hf = __bfloat162float(__float2bfloat16(v));
        g_w_hi[3][(size_t)n * DN + k] = __float2bfloat16(hf);
        g_w_lo[3][(size_t)n * DN + k] = __float2bfloat16(v - hf);
    }
}

__global__ void __launch_bounds__(256) vtrans_kernel()
{
    __shared__ __nv_bfloat16 th[32][33];
    __shared__ __nv_bfloat16 tl[32][33];
    int hb = blockIdx.z, h = hb >> 1, b = hb & 1;
    int s0 = blockIdx.x * 32, e0 = blockIdx.y * 32;
    int tx = threadIdx.x, ty = threadIdx.y;
#pragma unroll
    for (int i = 0; i < 4; i++) {
        size_t src = (size_t)(b * SN + s0 + ty + i * 8) * DN + h * EN + e0 + tx;
        th[ty + i * 8][tx] = g_p_hi[2][src];
        tl[ty + i * 8][tx] = g_p_lo[2][src];
    }
    __syncthreads();
#pragma unroll
    for (int i = 0; i < 4; i++) {
        int e = e0 + ty + i * 8;
        size_t dst = (size_t)e * SN + s0 + tx;
        g_vt_hi[hb][dst] = th[tx][ty + i * 8];
        g_vt_lo[hb][dst] = tl[tx][ty + i * 8];
    }
}

// ---------------------------------------------------------------------------
// Projection GEMM: 128x64 tile, 2-stage cp.async, 2 CTAs/SM. grid (32,16,3)
// ---------------------------------------------------------------------------
__device__ __forceinline__ void issue4_n64(uint32_t base,
    const __nv_bfloat16* ah, const __nv_bfloat16* al,
    const __nv_bfloat16* bh, const __nv_bfloat16* bl, int tid) {
    cp_tile(base,         ah, DN, tid, 128);
    cp_tile(base + 16384, al, DN, tid, 128);
    cp_tile(base + 32768, bh, DN, tid, 64);
    cp_tile(base + 40960, bl, DN, tid, 64);
}

__global__ void __launch_bounds__(256, 2) gemm_proj(int dummy)
{
    extern __shared__ char smem[];
    uint32_t sb = smem_u32(smem);
    int tid = threadIdx.x, wid = tid >> 5, lane = tid & 31;
    int z = blockIdx.z;
    const __nv_bfloat16* Axh = g_x_hi[z];
    const __nv_bfloat16* Axl = g_x_lo[z];
    const __nv_bfloat16* Bhi = g_w_hi[z];
    const __nv_bfloat16* Blo = g_w_lo[z];
    __nv_bfloat16* Chi = g_p_hi[z];
    __nv_bfloat16* Clo = g_p_lo[z];
    int m0 = blockIdx.x * 128, n0 = blockIdx.y * 64;
    int wm = wid & 3, wn = wid >> 2;

    issue4_n64(sb, Axh + (size_t)m0 * DN, Axl + (size_t)m0 * DN,
               Bhi + (size_t)n0 * DN, Blo + (size_t)n0 * DN, tid);
    CP_COMMIT();

    float acc[2][4][4] = {};
#pragma unroll 1
    for (int s = 0; s < 16; s++) {
        if (s < 15) {
            int kc = (s + 1) * 64;
            uint32_t nb = sb + ((s + 1) & 1) * NSTAGE;
            issue4_n64(nb, Axh + (size_t)m0 * DN + kc, Axl + (size_t)m0 * DN + kc,
                       Bhi + (size_t)n0 * DN + kc, Blo + (size_t)n0 * DN + kc, tid);
            CP_COMMIT();
            CP_WAIT1();
        } else {
            CP_WAIT0();
        }
        __syncthreads();
        mma_chunk_64(acc, sb + (s & 1) * NSTAGE, wm, wn, lane);
        __syncthreads();
    }

    size_t rbase = (size_t)m0 + wm * 32;
    int cbase = n0 + wn * 32;
#pragma unroll
    for (int mi = 0; mi < 2; mi++)
#pragma unroll
        for (int ni = 0; ni < 4; ni++) {
            size_t r0 = rbase + mi * 16 + (lane >> 2);
            int c = cbase + ni * 8 + (lane & 3) * 2;
            store_split2(Chi, Clo, r0 * DN + c,       acc[mi][ni][0], acc[mi][ni][1]);
            store_split2(Chi, Clo, (r0 + 8) * DN + c, acc[mi][ni][2], acc[mi][ni][3]);
        }
}

// ---------------------------------------------------------------------------
// Scores GEMM + fused exp + per-row partial sums. 128x128 tile, 2 CTAs/SM.
// Writes exp(s/64) to attn and per-(row, 32-col-group) sums to g_part.
// grid (16,16,32)
// ---------------------------------------------------------------------------
__global__ void __launch_bounds__(256, 2) gemm_scores(float* attn_arg)
{
    extern __shared__ char smem[];
    uint32_t sb = smem_u32(smem);
    int tid = threadIdx.x, wid = tid >> 5, lane = tid & 31;
    float* attn = attn_arg ? attn_arg : g_attn_fb;
    int hb = blockIdx.z, h = hb >> 1, b = hb & 1;
    int m0 = blockIdx.x * 128, n0 = blockIdx.y * 128;
    const __nv_bfloat16* Ah = g_p_hi[0] + (size_t)(b * SN + m0) * DN + h * EN;
    const __nv_bfloat16* Al = g_p_lo[0] + (size_t)(b * SN + m0) * DN + h * EN;
    const __nv_bfloat16* Bh = g_p_hi[1] + (size_t)(b * SN + n0) * DN + h * EN;
    const __nv_bfloat16* Bl = g_p_lo[1] + (size_t)(b * SN + n0) * DN + h * EN;
    float* C = attn + (size_t)hb * SN * SN;
    int wm = wid & 1, wn = wid >> 1;

    load_b16(sb,         Ah, DN, tid, 128);
    load_b16(sb + 16384, Al, DN, tid, 128);
    load_b16(sb + 32768, Bh, DN, tid, 128);
    load_b16(sb + 49152, Bl, DN, tid, 128);
    __syncthreads();

    float acc[4][4][4] = {};
    mma_chunk_128(acc, sb, wm, wn, lane);

    const float sc = 1.0f / 64.0f;
    size_t rbase = (size_t)m0 + wm * 64;
    int cbase = n0 + wn * 32;
    int cg = blockIdx.y * 4 + wn;   // 32-col group index, 0..63
#pragma unroll
    for (int mi = 0; mi < 4; mi++) {
        size_t r0 = rbase + mi * 16 + (lane >> 2);
        int c = cbase + mi * 0 + (lane & 3) * 2;   // column base per ni added below
        float s0 = 0.0f, s1 = 0.0f;
#pragma unroll
        for (int ni = 0; ni < 4; ni++) {
            float e0 = __expf(acc[mi][ni][0] * sc);
            float e1 = __expf(acc[mi][ni][1] * sc);
            float e2 = __expf(acc[mi][ni][2] * sc);
            float e3 = __expf(acc[mi][ni][3] * sc);
            int cc = c + ni * 8;
            *(float2*)(C + r0 * SN + cc)       = make_float2(e0, e1);
            *(float2*)(C + (r0 + 8) * SN + cc) = make_float2(e2, e3);
            s0 += e0 + e1;
            s1 += e2 + e3;
        }
        // reduce across the 4 lanes sharing each row (lane&3 group)
        s0 += __shfl_xor_sync(0xffffffffu, s0, 1);
        s0 += __shfl_xor_sync(0xffffffffu, s0, 2);
        s1 += __shfl_xor_sync(0xffffffffu, s1, 1);
        s1 += __shfl_xor_sync(0xffffffffu, s1, 2);
        if ((lane & 3) == 0) {
            g_part[(size_t)hb * SN + r0][cg]     = s0;
            g_part[(size_t)hb * SN + r0 + 8][cg] = s1;
        }
    }
}

// ---------------------------------------------------------------------------
// sumrows: g_inv[row] = 1 / sum(g_part[row][0..63]). grid (256), block 256.
// ---------------------------------------------------------------------------
__global__ void __launch_bounds__(256) sumrows_kernel()
{
    int row = blockIdx.x * 256 + threadIdx.x;   // 0 .. 65535
    const float4* p = (const float4*)g_part[row];
    float s = 0.0f;
#pragma unroll
    for (int i = 0; i < 16; i++) {
        float4 v = p[i];
        s += (v.x + v.y) + (v.z + v.w);
    }
    g_inv[row] = 1.0f / s;
}

// ---------------------------------------------------------------------------
// att GEMM: reads exp'd attn, normalizes (and writes back normalized attn),
// A normalized -> cat directly correct. 128x64 tile, 2-stage, 2 CTAs/SM.
// grid (16,1,32)
// ---------------------------------------------------------------------------
__global__ void __launch_bounds__(256, 2) gemm_att(float* attn_arg)
{
    extern __shared__ char smem[];
    __shared__ float sinv[128];
    uint32_t sb = smem_u32(smem);
    int tid = threadIdx.x, wid = tid >> 5, lane = tid & 31;
    float* attn = attn_arg ? attn_arg : g_attn_fb;
    int hb = blockIdx.z, h = hb >> 1, b = hb & 1;
    int m0 = blockIdx.x * 128;
    float* A = attn + (size_t)hb * SN * SN + (size_t)m0 * SN;
    int wm = wid & 3, wn = wid >> 2;

    if (tid < 128) sinv[tid] = g_inv[hb * SN + m0 + tid];
    cp_tile(sb + 32768, g_vt_hi[hb], SN, tid, 64);
    cp_tile(sb + 40960, g_vt_lo[hb], SN, tid, 64);
    CP_COMMIT();
    __syncthreads();   // sinv visible

    float acc[2][4][4] = {};
#pragma unroll 1
    for (int s = 0; s < 32; s++) {
        uint32_t bs = sb + (s & 1) * NSTAGE;
        storeA_norm(bs, bs + 16384, A + s * 64, SN, tid, sinv);
        if (s < 31) {
            int kc = (s + 1) * 64;
            uint32_t nb = sb + ((s + 1) & 1) * NSTAGE;
            cp_tile(nb + 32768, g_vt_hi[hb] + kc, SN, tid, 64);
            cp_tile(nb + 40960, g_vt_lo[hb] + kc, SN, tid, 64);
            CP_COMMIT();
            CP_WAIT1();
        } else {
            CP_WAIT0();
        }
        __syncthreads();
        mma_chunk_64(acc, bs, wm, wn, lane);
        __syncthreads();
    }

    size_t rbase = (size_t)(b * SN + m0) + wm * 32;
    int cbase = h * EN + wn * 32;
#pragma unroll
    for (int mi = 0; mi < 2; mi++)
#pragma unroll
        for (int ni = 0; ni < 4; ni++) {
            size_t r0 = rbase + mi * 16 + (lane >> 2);
            int c = cbase + ni * 8 + (lane & 3) * 2;
            store_split2(g_cat_hi, g_cat_lo, r0 * DN + c,       acc[mi][ni][0], acc[mi][ni][1]);
            store_split2(g_cat_hi, g_cat_lo, (r0 + 8) * DN + c, acc[mi][ni][2], acc[mi][ni][3]);
        }
}

// ---------------------------------------------------------------------------
// Output GEMM: 128x64 tile, 2-stage, 2 CTAs/SM. grid (32, 16)
// ---------------------------------------------------------------------------
__global__ void __launch_bounds__(256, 2) gemm_out(float* __restrict__ out)
{
    extern __shared__ char smem[];
    uint32_t sb = smem_u32(smem);
    int tid = threadIdx.x, wid = tid >> 5, lane = tid & 31;
    int m0 = blockIdx.x * 128, n0 = blockIdx.y * 64;
    int wm = wid & 3, wn = wid >> 2;

    issue4_n64(sb, g_cat_hi + (size_t)m0 * DN, g_cat_lo + (size_t)m0 * DN,
               g_w_hi[3] + (size_t)n0 * DN, g_w_lo[3] + (size_t)n0 * DN, tid);
    CP_COMMIT();

    float acc[2][4][4] = {};
#pragma unroll 1
    for (int s = 0; s < 16; s++) {
        if (s < 15) {
            int kc = (s + 1) * 64;
            uint32_t nb = sb + ((s + 1) & 1) * NSTAGE;
            issue4_n64(nb, g_cat_hi + (size_t)m0 * DN + kc, g_cat_lo + (size_t)m0 * DN + kc,
                       g_w_hi[3] + (size_t)n0 * DN + kc, g_w_lo[3] + (size_t)n0 * DN + kc, tid);
            CP_COMMIT();
            CP_WAIT1();
        } else {
            CP_WAIT0();
        }
        __syncthreads();
        mma_chunk_64(acc, sb + (s & 1) * NSTAGE, wm, wn, lane);
        __syncthreads();
    }

    size_t rbase = (size_t)m0 + wm * 32;
    int cbase = n0 + wn * 32;
#pragma unroll
    for (int mi = 0; mi < 2; mi++)
#pragma unroll
        for (int ni = 0; ni < 4; ni++) {
            size_t r0 = rbase + mi * 16 + (lane >> 2);
            int c = cbase + ni * 8 + (lane & 3) * 2;
            *(float2*)(out + r0 * DN + c)       = make_float2(acc[mi][ni][0], acc[mi][ni][1]);
            *(float2*)(out + (r0 + 8) * DN + c) = make_float2(acc[mi][ni][2], acc[mi][ni][3]);
        }
}

// ---------------------------------------------------------------------------
extern "C" void kernel_launch(void* const* d_in, const int* in_sizes, int n_in,
                              void* d_out, int out_size)
{
    const float* acts[3] = {nullptr, nullptr, nullptr};
    const float* wts[4]  = {nullptr, nullptr, nullptr, nullptr};
    int na = 0, nw = 0;
    for (int i = 0; i < n_in; i++) {
        if (in_sizes[i] == BSN * DN && na < 3) acts[na++] = (const float*)d_in[i];
        else if (nw < 4)                       wts[nw++]  = (const float*)d_in[i];
    }
    if (na != 3 || nw != 4) {
        acts[0] = (const float*)d_in[0]; acts[1] = (const float*)d_in[1]; acts[2] = (const float*)d_in[2];
        wts[0]  = (const float*)d_in[3]; wts[1]  = (const float*)d_in[4];
        wts[2]  = (const float*)d_in[5]; wts[3]  = (const float*)d_in[6];
    }
    const float* q  = acts[0];
    const float* k  = acts[1];
    const float* v  = acts[2];
    const float* Wq = wts[0];
    const float* Wk = wts[1];
    const float* Wv = wts[2];
    const float* Wo = wts[3];
    float* out = (float*)d_out;

    const long long OUT_E  = (long long)BSN * DN;
    const long long ATTN_E = (long long)HBN * SN * SN;
    float* attn_ptr = ((long long)out_size >= OUT_E + ATTN_E) ? (out + OUT_E) : nullptr;

    cudaFuncSetAttribute(gemm_proj,   cudaFuncAttributeMaxDynamicSharedMemorySize, SMEM_N64X2);
    cudaFuncSetAttribute(gemm_scores, cudaFuncAttributeMaxDynamicSharedMemorySize, SMEM_SCORES);
    cudaFuncSetAttribute(gemm_att,    cudaFuncAttributeMaxDynamicSharedMemorySize, SMEM_N64X2);
    cudaFuncSetAttribute(gemm_out,    cudaFuncAttributeMaxDynamicSharedMemorySize, SMEM_N64X2);

    xsplit_kernel<<<dim3(2048, 3), 256>>>(q, k, v);
    wsplit_qkv<<<dim3(32, 2, 48), dim3(32, 8)>>>(Wq, Wk, Wv);
    wsplit_o<<<dim3(32, 32), dim3(32, 8)>>>(Wo);
    gemm_proj<<<dim3(32, 16, 3), 256, SMEM_N64X2>>>(0);
    vtrans_kernel<<<dim3(64, 2, 32), dim3(32, 8)>>>();
    gemm_scores<<<dim3(16, 16, 32), 256, SMEM_SCORES>>>(attn_ptr);
    sumrows_kernel<<<dim3(256), 256>>>();
    gemm_att<<<dim3(16, 1, 32), 256, SMEM_N64X2>>>(attn_ptr);
    gemm_out<<<dim3(32, 16), 256, SMEM_N64X2>>>(out);
}

// round 17
// speedup vs baseline: 1.1638x; 1.1638x over previous
#include <cuda_runtime.h>
#include <cuda_bf16.h>
#include <cstdint>

#define HN 16
#define BN_ 2
#define SN 2048
#define DN 1024
#define EN 64
#define BSN 4096
#define HBN 32

// ---------------- device scratch (allocation-free rule) ----------------
__device__ __align__(256) __nv_bfloat16 g_w_hi[4][DN * DN];   // [z][n][k]
__device__ __align__(256) __nv_bfloat16 g_w_lo[4][DN * DN];
__device__ __align__(256) __nv_bfloat16 g_x_hi[3][BSN * DN];  // q/k/v split [b*S+s][d]
__device__ __align__(256) __nv_bfloat16 g_x_lo[3][BSN * DN];
__device__ __align__(256) __nv_bfloat16 g_p_hi[3][BSN * DN];  // qh/kh/vh split
__device__ __align__(256) __nv_bfloat16 g_p_lo[3][BSN * DN];
__device__ __align__(256) __nv_bfloat16 g_vt_hi[HBN][EN * SN]; // V^T per head
__device__ __align__(256) __nv_bfloat16 g_vt_lo[HBN][EN * SN];
__device__ __align__(256) __nv_bfloat16 g_cat_hi[BSN * DN];
__device__ __align__(256) __nv_bfloat16 g_cat_lo[BSN * DN];
__device__ __align__(256) float g_attn_fb[(size_t)HBN * SN * SN];

// ---------------- helpers ----------------
__device__ __forceinline__ uint32_t smem_u32(const void* p) {
    uint32_t a;
    asm("{ .reg .u64 t; cvta.to.shared.u64 t, %1; cvt.u32.u64 %0, t; }" : "=r"(a) : "l"(p));
    return a;
}
#define SWZ(x) ((x) ^ (((x) >> 3) & 0x70))

__device__ __forceinline__ void sts128(uint32_t addr, uint4 v) {
    asm volatile("st.shared.v4.b32 [%0], {%1,%2,%3,%4};"
                 :: "r"(addr), "r"(v.x), "r"(v.y), "r"(v.z), "r"(v.w) : "memory");
}
__device__ __forceinline__ uint32_t bpair(float a, float b) {
    uint32_t r;
    asm("cvt.rn.bf16x2.f32 %0, %1, %2;" : "=r"(r) : "f"(b), "f"(a));
    return r;
}
__device__ __forceinline__ void ldmx4(uint32_t* r, uint32_t addr) {
    asm volatile("ldmatrix.sync.aligned.m8n8.x4.shared.b16 {%0,%1,%2,%3}, [%4];"
                 : "=r"(r[0]), "=r"(r[1]), "=r"(r[2]), "=r"(r[3]) : "r"(addr));
}
__device__ __forceinline__ void mma16816(float* d, const uint32_t* a, const uint32_t* b) {
    asm volatile("mma.sync.aligned.m16n8k16.row.col.f32.bf16.bf16.f32 "
        "{%0,%1,%2,%3}, {%4,%5,%6,%7}, {%8,%9}, {%0,%1,%2,%3};"
        : "+f"(d[0]), "+f"(d[1]), "+f"(d[2]), "+f"(d[3])
        : "r"(a[0]), "r"(a[1]), "r"(a[2]), "r"(a[3]), "r"(b[0]), "r"(b[1]));
}
__device__ __forceinline__ void store_split2(__nv_bfloat16* Chi, __nv_bfloat16* Clo,
                                             size_t off, float v0, float v1) {
    float h0 = __bfloat162float(__float2bfloat16(v0));
    float h1 = __bfloat162float(__float2bfloat16(v1));
    *(uint32_t*)(Chi + off) = bpair(h0, h1);
    *(uint32_t*)(Clo + off) = bpair(v0 - h0, v1 - h1);
}

// cp.async 16B
__device__ __forceinline__ void cpa16(uint32_t dst, const void* src) {
    asm volatile("cp.async.cg.shared.global [%0], [%1], 16;" :: "r"(dst), "l"(src) : "memory");
}
#define CP_COMMIT() asm volatile("cp.async.commit_group;" ::: "memory")
#define CP_WAIT1()  asm volatile("cp.async.wait_group 1;" ::: "memory")
#define CP_WAIT0()  asm volatile("cp.async.wait_group 0;" ::: "memory")

__device__ __forceinline__ void cp_tile(uint32_t dst, const __nv_bfloat16* __restrict__ src,
                                        int ld, int tid, int rows) {
    int nchunk = rows * 8;
    for (int c = tid; c < nchunk; c += 256) {
        int r = c >> 3, g = c & 7;
        cpa16(dst + SWZ((uint32_t)(r * 128 + g * 16)), src + (size_t)r * ld + g * 8);
    }
}
__device__ __forceinline__ void load_b16(uint32_t dst, const __nv_bfloat16* __restrict__ src,
                                         int ld, int tid, int rows) {
    int nchunk = rows * 8;
    for (int c = tid; c < nchunk; c += 256) {
        int r = c >> 3, g = c & 7;
        uint4 v = *(const uint4*)(src + (size_t)r * ld + g * 8);
        sts128(dst + SWZ((uint32_t)(r * 128 + g * 16)), v);
    }
}

// direct global fp32 -> split bf16 hi/lo swizzled smem (128 rows x 64 cols)
__device__ __forceinline__ void storeA_direct(uint32_t dhi, uint32_t dlo,
                                              const float* __restrict__ src, int ld, int tid) {
#pragma unroll
    for (int it = 0; it < 4; it++) {
        int c = tid + it * 256;
        int r = c >> 3, g = c & 7;
        const float* p = src + (size_t)r * ld + g * 8;
        float4 f0 = *(const float4*)p;
        float4 f1 = *(const float4*)(p + 4);
        float v[8] = {f0.x, f0.y, f0.z, f0.w, f1.x, f1.y, f1.z, f1.w};
        uint4 H, L;
        uint32_t* Hp = (uint32_t*)&H;
        uint32_t* Lp = (uint32_t*)&L;
#pragma unroll
        for (int pp = 0; pp < 4; pp++) {
            float h0 = __bfloat162float(__float2bfloat16(v[pp * 2]));
            float h1 = __bfloat162float(__float2bfloat16(v[pp * 2 + 1]));
            Hp[pp] = bpair(h0, h1);
            Lp[pp] = bpair(v[pp * 2] - h0, v[pp * 2 + 1] - h1);
        }
        uint32_t ad = SWZ((uint32_t)(r * 128 + g * 16));
        sts128(dhi + ad, H);
        sts128(dlo + ad, L);
    }
}

// smem layouts
#define NSTAGE 49152
#define SMEM_N64X2 (2 * NSTAGE)   // 96 KB -> 2 CTAs/SM
#define SMEM_SCORES 65536         // 128x128 single stage; 2 CTAs/SM via reg cap

// ===========================================================================
// mma core, 128x64 tile, 8 warps (4x2), warp 32x32. acc[2][4][4].
// ===========================================================================
__device__ __forceinline__ void mma_chunk_64(float acc[2][4][4], uint32_t bs,
                                             int wm, int wn, int lane) {
#pragma unroll
    for (int ks = 0; ks < 4; ks++) {
        uint32_t ah[2][4], al[2][4], bh[4][2], bl[4][2];
        int acol = ks * 32 + (lane >> 4) * 16;
#pragma unroll
        for (int mi = 0; mi < 2; mi++) {
            int arow = wm * 32 + mi * 16 + (lane & 15);
            uint32_t off = SWZ((uint32_t)(arow * 128 + acol));
            ldmx4(ah[mi], bs + off);
            ldmx4(al[mi], bs + 16384 + off);
        }
        int bcol = ks * 32 + ((lane >> 3) & 1) * 16;
#pragma unroll
        for (int nj = 0; nj < 2; nj++) {
            int brow = wn * 32 + nj * 16 + (lane & 7) + (lane >> 4) * 8;
            uint32_t off = SWZ((uint32_t)(brow * 128 + bcol));
            uint32_t t[4];
            ldmx4(t, bs + 32768 + off);
            bh[nj * 2][0] = t[0]; bh[nj * 2][1] = t[1];
            bh[nj * 2 + 1][0] = t[2]; bh[nj * 2 + 1][1] = t[3];
            ldmx4(t, bs + 40960 + off);
            bl[nj * 2][0] = t[0]; bl[nj * 2][1] = t[1];
            bl[nj * 2 + 1][0] = t[2]; bl[nj * 2 + 1][1] = t[3];
        }
#pragma unroll
        for (int mi = 0; mi < 2; mi++)
#pragma unroll
            for (int ni = 0; ni < 4; ni++) {
                mma16816(acc[mi][ni], ah[mi], bh[ni]);
                mma16816(acc[mi][ni], ah[mi], bl[ni]);
                mma16816(acc[mi][ni], al[mi], bh[ni]);
            }
    }
}

// mma core, 128x128 tile (scores), 8 warps (2x4), warp 64x32. acc[4][4][4].
__device__ __forceinline__ void mma_chunk_128(float acc[4][4][4], uint32_t bs,
                                              int wm, int wn, int lane) {
#pragma unroll
    for (int ks = 0; ks < 4; ks++) {
        uint32_t ah[4][4], al[4][4], bh[4][2], bl[4][2];
        int acol = ks * 32 + (lane >> 4) * 16;
#pragma unroll
        for (int mi = 0; mi < 4; mi++) {
            int arow = wm * 64 + mi * 16 + (lane & 15);
            uint32_t off = SWZ((uint32_t)(arow * 128 + acol));
            ldmx4(ah[mi], bs + off);
            ldmx4(al[mi], bs + 16384 + off);
        }
        int bcol = ks * 32 + ((lane >> 3) & 1) * 16;
#pragma unroll
        for (int nj = 0; nj < 2; nj++) {
            int brow = wn * 32 + nj * 16 + (lane & 7) + (lane >> 4) * 8;
            uint32_t off = SWZ((uint32_t)(brow * 128 + bcol));
            uint32_t t[4];
            ldmx4(t, bs + 32768 + off);
            bh[nj * 2][0] = t[0]; bh[nj * 2][1] = t[1];
            bh[nj * 2 + 1][0] = t[2]; bh[nj * 2 + 1][1] = t[3];
            ldmx4(t, bs + 49152 + off);
            bl[nj * 2][0] = t[0]; bl[nj * 2][1] = t[1];
            bl[nj * 2 + 1][0] = t[2]; bl[nj * 2 + 1][1] = t[3];
        }
#pragma unroll
        for (int mi = 0; mi < 4; mi++)
#pragma unroll
            for (int ni = 0; ni < 4; ni++) {
                mma16816(acc[mi][ni], ah[mi], bh[ni]);
                mma16816(acc[mi][ni], ah[mi], bl[ni]);
                mma16816(acc[mi][ni], al[mi], bh[ni]);
            }
    }
}

// ---------------------------------------------------------------------------
// xsplit: q/k/v fp32 -> bf16 hi/lo. grid (2048, 3)
// ---------------------------------------------------------------------------
__global__ void __launch_bounds__(256) xsplit_kernel(
    const float* __restrict__ q, const float* __restrict__ k, const float* __restrict__ v)
{
    int z = blockIdx.y;
    const float* X = (z == 0) ? q : ((z == 1) ? k : v);
    size_t idx = ((size_t)blockIdx.x * 256 + threadIdx.x) * 8;
    float4 f0 = *(const float4*)(X + idx);
    float4 f1 = *(const float4*)(X + idx + 4);
    float val[8] = {f0.x, f0.y, f0.z, f0.w, f1.x, f1.y, f1.z, f1.w};
    uint4 H, L;
    uint32_t* Hp = (uint32_t*)&H;
    uint32_t* Lp = (uint32_t*)&L;
#pragma unroll
    for (int pp = 0; pp < 4; pp++) {
        float h0 = __bfloat162float(__float2bfloat16(val[pp * 2]));
        float h1 = __bfloat162float(__float2bfloat16(val[pp * 2 + 1]));
        Hp[pp] = bpair(h0, h1);
        Lp[pp] = bpair(val[pp * 2] - h0, val[pp * 2 + 1] - h1);
    }
    *(uint4*)(g_x_hi[z] + idx) = H;
    *(uint4*)(g_x_lo[z] + idx) = L;
}

// ---------------------------------------------------------------------------
// Weight transpose+split (unchanged)
// ---------------------------------------------------------------------------
__global__ void __launch_bounds__(256) wsplit_qkv(
    const float* __restrict__ wq, const float* __restrict__ wk, const float* __restrict__ wv)
{
    __shared__ float tile[32][33];
    int z = blockIdx.z >> 4, h = blockIdx.z & 15;
    const float* W = (z == 0) ? wq : ((z == 1) ? wk : wv);
    int d0 = blockIdx.x * 32, e0 = blockIdx.y * 32;
    int tx = threadIdx.x, ty = threadIdx.y;
#pragma unroll
    for (int i = 0; i < 4; i++) {
        int d = d0 + ty + i * 8;
        tile[ty + i * 8][tx] = W[(size_t)h * DN * EN + (size_t)d * EN + e0 + tx];
    }
    __syncthreads();
#pragma unroll
    for (int i = 0; i < 4; i++) {
        int e = e0 + ty + i * 8;
        int n = h * EN + e, k = d0 + tx;
        float v = tile[tx][ty + i * 8];
        float hf = __bfloat162float(__float2bfloat16(v));
        g_w_hi[z][(size_t)n * DN + k] = __float2bfloat16(hf);
        g_w_lo[z][(size_t)n * DN + k] = __float2bfloat16(v - hf);
    }
}

__global__ void __launch_bounds__(256) wsplit_o(const float* __restrict__ wo)
{
    __shared__ float tile[32][33];
    int k0 = blockIdx.x * 32, n0 = blockIdx.y * 32;
    int tx = threadIdx.x, ty = threadIdx.y;
#pragma unroll
    for (int i = 0; i < 4; i++)
        tile[ty + i * 8][tx] = wo[(size_t)(k0 + ty + i * 8) * DN + n0 + tx];
    __syncthreads();
#pragma unroll
    for (int i = 0; i < 4; i++) {
        int n = n0 + ty + i * 8, k = k0 + tx;
        float v = tile[tx][ty + i * 8];
        float hf = __bfloat162float(__float2bfloat16(v));
        g_w_hi[3][(size_t)n * DN + k] = __float2bfloat16(hf);
        g_w_lo[3][(size_t)n * DN + k] = __float2bfloat16(v - hf);
    }
}

__global__ void __launch_bounds__(256) vtrans_kernel()
{
    __shared__ __nv_bfloat16 th[32][33];
    __shared__ __nv_bfloat16 tl[32][33];
    int hb = blockIdx.z, h = hb >> 1, b = hb & 1;
    int s0 = blockIdx.x * 32, e0 = blockIdx.y * 32;
    int tx = threadIdx.x, ty = threadIdx.y;
#pragma unroll
    for (int i = 0; i < 4; i++) {
        size_t src = (size_t)(b * SN + s0 + ty + i * 8) * DN + h * EN + e0 + tx;
        th[ty + i * 8][tx] = g_p_hi[2][src];
        tl[ty + i * 8][tx] = g_p_lo[2][src];
    }
    __syncthreads();
#pragma unroll
    for (int i = 0; i < 4; i++) {
        int e = e0 + ty + i * 8;
        size_t dst = (size_t)e * SN + s0 + tx;
        g_vt_hi[hb][dst] = th[tx][ty + i * 8];
        g_vt_lo[hb][dst] = tl[tx][ty + i * 8];
    }
}

// ---------------------------------------------------------------------------
// Projection GEMM: 128x64 tile, 2-stage cp.async, 2 CTAs/SM. grid (32,16,3)
// ---------------------------------------------------------------------------
__device__ __forceinline__ void issue4_n64(uint32_t base,
    const __nv_bfloat16* ah, const __nv_bfloat16* al,
    const __nv_bfloat16* bh, const __nv_bfloat16* bl, int tid) {
    cp_tile(base,         ah, DN, tid, 128);
    cp_tile(base + 16384, al, DN, tid, 128);
    cp_tile(base + 32768, bh, DN, tid, 64);
    cp_tile(base + 40960, bl, DN, tid, 64);
}

__global__ void __launch_bounds__(256, 2) gemm_proj(int dummy)
{
    extern __shared__ char smem[];
    uint32_t sb = smem_u32(smem);
    int tid = threadIdx.x, wid = tid >> 5, lane = tid & 31;
    int z = blockIdx.z;
    const __nv_bfloat16* Axh = g_x_hi[z];
    const __nv_bfloat16* Axl = g_x_lo[z];
    const __nv_bfloat16* Bhi = g_w_hi[z];
    const __nv_bfloat16* Blo = g_w_lo[z];
    __nv_bfloat16* Chi = g_p_hi[z];
    __nv_bfloat16* Clo = g_p_lo[z];
    int m0 = blockIdx.x * 128, n0 = blockIdx.y * 64;
    int wm = wid & 3, wn = wid >> 2;

    issue4_n64(sb, Axh + (size_t)m0 * DN, Axl + (size_t)m0 * DN,
               Bhi + (size_t)n0 * DN, Blo + (size_t)n0 * DN, tid);
    CP_COMMIT();

    float acc[2][4][4] = {};
#pragma unroll 1
    for (int s = 0; s < 16; s++) {
        if (s < 15) {
            int kc = (s + 1) * 64;
            uint32_t nb = sb + ((s + 1) & 1) * NSTAGE;
            issue4_n64(nb, Axh + (size_t)m0 * DN + kc, Axl + (size_t)m0 * DN + kc,
                       Bhi + (size_t)n0 * DN + kc, Blo + (size_t)n0 * DN + kc, tid);
            CP_COMMIT();
            CP_WAIT1();
        } else {
            CP_WAIT0();
        }
        __syncthreads();
        mma_chunk_64(acc, sb + (s & 1) * NSTAGE, wm, wn, lane);
        __syncthreads();
    }

    size_t rbase = (size_t)m0 + wm * 32;
    int cbase = n0 + wn * 32;
#pragma unroll
    for (int mi = 0; mi < 2; mi++)
#pragma unroll
        for (int ni = 0; ni < 4; ni++) {
            size_t r0 = rbase + mi * 16 + (lane >> 2);
            int c = cbase + ni * 8 + (lane & 3) * 2;
            store_split2(Chi, Clo, r0 * DN + c,       acc[mi][ni][0], acc[mi][ni][1]);
            store_split2(Chi, Clo, (r0 + 8) * DN + c, acc[mi][ni][2], acc[mi][ni][3]);
        }
}

// ---------------------------------------------------------------------------
// Scores GEMM: 128x128 tile, reg-capped 2 CTAs/SM, cp.async bulk tile loads.
// grid (16,16,32)
// ---------------------------------------------------------------------------
__global__ void __launch_bounds__(256, 2) gemm_scores(float* attn_arg)
{
    extern __shared__ char smem[];
    uint32_t sb = smem_u32(smem);
    int tid = threadIdx.x, wid = tid >> 5, lane = tid & 31;
    float* attn = attn_arg ? attn_arg : g_attn_fb;
    int hb = blockIdx.z, h = hb >> 1, b = hb & 1;
    int m0 = blockIdx.x * 128, n0 = blockIdx.y * 128;
    const __nv_bfloat16* Ah = g_p_hi[0] + (size_t)(b * SN + m0) * DN + h * EN;
    const __nv_bfloat16* Al = g_p_lo[0] + (size_t)(b * SN + m0) * DN + h * EN;
    const __nv_bfloat16* Bh = g_p_hi[1] + (size_t)(b * SN + n0) * DN + h * EN;
    const __nv_bfloat16* Bl = g_p_lo[1] + (size_t)(b * SN + n0) * DN + h * EN;
    float* C = attn + (size_t)hb * SN * SN;
    int wm = wid & 1, wn = wid >> 1;

    cp_tile(sb,         Ah, DN, tid, 128);
    cp_tile(sb + 16384, Al, DN, tid, 128);
    cp_tile(sb + 32768, Bh, DN, tid, 128);
    cp_tile(sb + 49152, Bl, DN, tid, 128);
    CP_COMMIT();
    CP_WAIT0();
    __syncthreads();

    float acc[4][4][4] = {};
    mma_chunk_128(acc, sb, wm, wn, lane);

    const float sc = 1.0f / 64.0f;
    size_t rbase = (size_t)m0 + wm * 64;
    int cbase = n0 + wn * 32;
#pragma unroll
    for (int mi = 0; mi < 4; mi++)
#pragma unroll
        for (int ni = 0; ni < 4; ni++) {
            size_t r0 = rbase + mi * 16 + (lane >> 2);
            int c = cbase + ni * 8 + (lane & 3) * 2;
            *(float2*)(C + r0 * SN + c)       = make_float2(acc[mi][ni][0] * sc, acc[mi][ni][1] * sc);
            *(float2*)(C + (r0 + 8) * SN + c) = make_float2(acc[mi][ni][2] * sc, acc[mi][ni][3] * sc);
        }
}

// ---------------------------------------------------------------------------
// Row softmax: one WARP per row, 64 elems/thread in registers, 8 rows/block.
// grid (HBN*SN/8) = 8192 blocks of 256 threads.
// ---------------------------------------------------------------------------
__global__ void __launch_bounds__(256) softmax_kernel(float* attn_arg)
{
    float* attn = attn_arg ? attn_arg : g_attn_fb;
    int w = threadIdx.x >> 5, lane = threadIdx.x & 31;
    size_t row = (size_t)blockIdx.x * 8 + w;
    float* p = attn + row * (size_t)SN;

    float4 v[16];
#pragma unroll
    for (int i = 0; i < 16; i++)
        v[i] = *(float4*)(p + (size_t)(i * 32 + lane) * 4);

    float m = -3.0e38f;
#pragma unroll
    for (int i = 0; i < 16; i++)
        m = fmaxf(m, fmaxf(fmaxf(v[i].x, v[i].y), fmaxf(v[i].z, v[i].w)));
#pragma unroll
    for (int o = 16; o > 0; o >>= 1) m = fmaxf(m, __shfl_xor_sync(0xffffffffu, m, o));

    float s = 0.0f;
#pragma unroll
    for (int i = 0; i < 16; i++) {
        v[i].x = __expf(v[i].x - m);
        v[i].y = __expf(v[i].y - m);
        v[i].z = __expf(v[i].z - m);
        v[i].w = __expf(v[i].w - m);
        s += (v[i].x + v[i].y) + (v[i].z + v[i].w);
    }
#pragma unroll
    for (int o = 16; o > 0; o >>= 1) s += __shfl_xor_sync(0xffffffffu, s, o);
    float inv = 1.0f / s;

#pragma unroll
    for (int i = 0; i < 16; i++) {
        v[i].x *= inv; v[i].y *= inv; v[i].z *= inv; v[i].w *= inv;
        *(float4*)(p + (size_t)(i * 32 + lane) * 4) = v[i];
    }
}

// ---------------------------------------------------------------------------
// att GEMM: 128x64 tile, 2-stage B cp.async, A converted direct from global.
// 2 CTAs/SM cover the conversion latency. grid (16,1,32)
// ---------------------------------------------------------------------------
__global__ void __launch_bounds__(256, 2) gemm_att(const float* attn_arg)
{
    extern __shared__ char smem[];
    uint32_t sb = smem_u32(smem);
    int tid = threadIdx.x, wid = tid >> 5, lane = tid & 31;
    const float* attn = attn_arg ? attn_arg : g_attn_fb;
    int hb = blockIdx.z, h = hb >> 1, b = hb & 1;
    int m0 = blockIdx.x * 128;
    const float* A = attn + (size_t)hb * SN * SN + (size_t)m0 * SN;
    int wm = wid & 3, wn = wid >> 2;

    cp_tile(sb + 32768, g_vt_hi[hb], SN, tid, 64);
    cp_tile(sb + 40960, g_vt_lo[hb], SN, tid, 64);
    CP_COMMIT();

    float acc[2][4][4] = {};
#pragma unroll 1
    for (int s = 0; s < 32; s++) {
        uint32_t bs = sb + (s & 1) * NSTAGE;
        storeA_direct(bs, bs + 16384, A + s * 64, SN, tid);
        if (s < 31) {
            int kc = (s + 1) * 64;
            uint32_t nb = sb + ((s + 1) & 1) * NSTAGE;
            cp_tile(nb + 32768, g_vt_hi[hb] + kc, SN, tid, 64);
            cp_tile(nb + 40960, g_vt_lo[hb] + kc, SN, tid, 64);
            CP_COMMIT();
            CP_WAIT1();
        } else {
            CP_WAIT0();
        }
        __syncthreads();
        mma_chunk_64(acc, bs, wm, wn, lane);
        __syncthreads();
    }

    size_t rbase = (size_t)(b * SN + m0) + wm * 32;
    int cbase = h * EN + wn * 32;
#pragma unroll
    for (int mi = 0; mi < 2; mi++)
#pragma unroll
        for (int ni = 0; ni < 4; ni++) {
            size_t r0 = rbase + mi * 16 + (lane >> 2);
            int c = cbase + ni * 8 + (lane & 3) * 2;
            store_split2(g_cat_hi, g_cat_lo, r0 * DN + c,       acc[mi][ni][0], acc[mi][ni][1]);
            store_split2(g_cat_hi, g_cat_lo, (r0 + 8) * DN + c, acc[mi][ni][2], acc[mi][ni][3]);
        }
}

// ---------------------------------------------------------------------------
// Output GEMM: 128x64 tile, 2-stage, 2 CTAs/SM. grid (32, 16)
// ---------------------------------------------------------------------------
__global__ void __launch_bounds__(256, 2) gemm_out(float* __restrict__ out)
{
    extern __shared__ char smem[];
    uint32_t sb = smem_u32(smem);
    int tid = threadIdx.x, wid = tid >> 5, lane = tid & 31;
    int m0 = blockIdx.x * 128, n0 = blockIdx.y * 64;
    int wm = wid & 3, wn = wid >> 2;

    issue4_n64(sb, g_cat_hi + (size_t)m0 * DN, g_cat_lo + (size_t)m0 * DN,
               g_w_hi[3] + (size_t)n0 * DN, g_w_lo[3] + (size_t)n0 * DN, tid);
    CP_COMMIT();

    float acc[2][4][4] = {};
#pragma unroll 1
    for (int s = 0; s < 16; s++) {
        if (s < 15) {
            int kc = (s + 1) * 64;
            uint32_t nb = sb + ((s + 1) & 1) * NSTAGE;
            issue4_n64(nb, g_cat_hi + (size_t)m0 * DN + kc, g_cat_lo + (size_t)m0 * DN + kc,
                       g_w_hi[3] + (size_t)n0 * DN + kc, g_w_lo[3] + (size_t)n0 * DN + kc, tid);
            CP_COMMIT();
            CP_WAIT1();
        } else {
            CP_WAIT0();
        }
        __syncthreads();
        mma_chunk_64(acc, sb + (s & 1) * NSTAGE, wm, wn, lane);
        __syncthreads();
    }

    size_t rbase = (size_t)m0 + wm * 32;
    int cbase = n0 + wn * 32;
#pragma unroll
    for (int mi = 0; mi < 2; mi++)
#pragma unroll
        for (int ni = 0; ni < 4; ni++) {
            size_t r0 = rbase + mi * 16 + (lane >> 2);
            int c = cbase + ni * 8 + (lane & 3) * 2;
            *(float2*)(out + r0 * DN + c)       = make_float2(acc[mi][ni][0], acc[mi][ni][1]);
            *(float2*)(out + (r0 + 8) * DN + c) = make_float2(acc[mi][ni][2], acc[mi][ni][3]);
        }
}

// ---------------------------------------------------------------------------
extern "C" void kernel_launch(void* const* d_in, const int* in_sizes, int n_in,
                              void* d_out, int out_size)
{
    const float* acts[3] = {nullptr, nullptr, nullptr};
    const float* wts[4]  = {nullptr, nullptr, nullptr, nullptr};
    int na = 0, nw = 0;
    for (int i = 0; i < n_in; i++) {
        if (in_sizes[i] == BSN * DN && na < 3) acts[na++] = (const float*)d_in[i];
        else if (nw < 4)                       wts[nw++]  = (const float*)d_in[i];
    }
    if (na != 3 || nw != 4) {
        acts[0] = (const float*)d_in[0]; acts[1] = (const float*)d_in[1]; acts[2] = (const float*)d_in[2];
        wts[0]  = (const float*)d_in[3]; wts[1]  = (const float*)d_in[4];
        wts[2]  = (const float*)d_in[5]; wts[3]  = (const float*)d_in[6];
    }
    const float* q  = acts[0];
    const float* k  = acts[1];
    const float* v  = acts[2];
    const float* Wq = wts[0];
    const float* Wk = wts[1];
    const float* Wv = wts[2];
    const float* Wo = wts[3];
    float* out = (float*)d_out;

    const long long OUT_E  = (long long)BSN * DN;
    const long long ATTN_E = (long long)HBN * SN * SN;
    float* attn_ptr = ((long long)out_size >= OUT_E + ATTN_E) ? (out + OUT_E) : nullptr;

    cudaFuncSetAttribute(gemm_proj,   cudaFuncAttributeMaxDynamicSharedMemorySize, SMEM_N64X2);
    cudaFuncSetAttribute(gemm_scores, cudaFuncAttributeMaxDynamicSharedMemorySize, SMEM_SCORES);
    cudaFuncSetAttribute(gemm_att,    cudaFuncAttributeMaxDynamicSharedMemorySize, SMEM_N64X2);
    cudaFuncSetAttribute(gemm_out,    cudaFuncAttributeMaxDynamicSharedMemorySize, SMEM_N64X2);

    xsplit_kernel<<<dim3(2048, 3), 256>>>(q, k, v);
    wsplit_qkv<<<dim3(32, 2, 48), dim3(32, 8)>>>(Wq, Wk, Wv);
    wsplit_o<<<dim3(32, 32), dim3(32, 8)>>>(Wo);
    gemm_proj<<<dim3(32, 16, 3), 256, SMEM_N64X2>>>(0);
    vtrans_kernel<<<dim3(64, 2, 32), dim3(32, 8)>>>();
    gemm_scores<<<dim3(16, 16, 32), 256, SMEM_SCORES>>>(attn_ptr);
    softmax_kernel<<<dim3(HBN * SN / 8), 256>>>(attn_ptr);
    gemm_att<<<dim3(16, 1, 32), 256, SMEM_N64X2>>>(attn_ptr);
    gemm_out<<<dim3(32, 16), 256, SMEM_N64X2>>>(out);
}